// round 15
// baseline (speedup 1.0000x reference)
#include <cuda_runtime.h>
#include <cuda_fp16.h>
#include <math.h>
#include <cstdint>

// Problem constants
#define BATCH 4
#define SEQ   2048
#define HID   1024
#define NHEAD 16
#define DK    64
#define DFF   4096
#define MTOT  (BATCH * SEQ)          // 8192 rows
#define NQKV  (3 * HID)              // 3072

// ---------------------------------------------------------------------------
// Scratch
// ---------------------------------------------------------------------------
__device__ __half g_xh  [MTOT * HID];
__device__ __half g_qkvh[MTOT * NQKV];
__device__ __half g_ctxh[MTOT * HID];
__device__ __half g_aoh [MTOT * HID];
__device__ float  g_x1  [MTOT * HID];
__device__ __half g_x1h [MTOT * HID];
__device__ __half g_hh  [MTOT * DFF];
__device__ __half g_ffh [MTOT * HID];
__device__ __half g_wqkvt[NQKV * HID];
__device__ __half g_wot [HID * HID];
__device__ __half g_w1t [HID * DFF];
__device__ __half g_w2t [DFF * HID];
__device__ float  g_bqkv[NQKV];

// ---------------------------------------------------------------------------
// helpers
// ---------------------------------------------------------------------------
__device__ __forceinline__ uint32_t smem_u32(const void* p) {
    uint32_t a;
    asm("{ .reg .u64 t; cvta.to.shared.u64 t, %1; cvt.u32.u64 %0, t; }" : "=r"(a) : "l"(p));
    return a;
}
__device__ __forceinline__ void cp_async16(uint32_t saddr, const void* gaddr) {
    asm volatile("cp.async.cg.shared.global [%0], [%1], 16;" :: "r"(saddr), "l"(gaddr) : "memory");
}
#define CP_COMMIT() asm volatile("cp.async.commit_group;" ::: "memory")
#define CP_WAIT(n)  asm volatile("cp.async.wait_group %0;" :: "n"(n) : "memory")

__device__ __forceinline__ void mma_f16(
    float& d0, float& d1, float& d2, float& d3,
    uint32_t a0, uint32_t a1, uint32_t a2, uint32_t a3,
    uint32_t b0, uint32_t b1)
{
    asm volatile(
        "mma.sync.aligned.m16n8k16.row.col.f32.f16.f16.f32 "
        "{%0,%1,%2,%3}, {%4,%5,%6,%7}, {%8,%9}, {%0,%1,%2,%3};"
        : "+f"(d0), "+f"(d1), "+f"(d2), "+f"(d3)
        : "r"(a0), "r"(a1), "r"(a2), "r"(a3), "r"(b0), "r"(b1));
}
// fp16 accumulator variant (2x issue rate on half-rate-f32 parts)
__device__ __forceinline__ void mma_f16acc(
    uint32_t& d0, uint32_t& d1,
    uint32_t a0, uint32_t a1, uint32_t a2, uint32_t a3,
    uint32_t b0, uint32_t b1)
{
    asm volatile(
        "mma.sync.aligned.m16n8k16.row.col.f16.f16.f16.f16 "
        "{%0,%1}, {%2,%3,%4,%5}, {%6,%7}, {%0,%1};"
        : "+r"(d0), "+r"(d1)
        : "r"(a0), "r"(a1), "r"(a2), "r"(a3), "r"(b0), "r"(b1));
}
__device__ __forceinline__ void ldmatrix_x4(
    uint32_t& r0, uint32_t& r1, uint32_t& r2, uint32_t& r3, uint32_t addr)
{
    asm volatile("ldmatrix.sync.aligned.m8n8.x4.shared.b16 {%0,%1,%2,%3}, [%4];"
                 : "=r"(r0), "=r"(r1), "=r"(r2), "=r"(r3) : "r"(addr));
}
__device__ __forceinline__ void ldmatrix_x4_trans(
    uint32_t& r0, uint32_t& r1, uint32_t& r2, uint32_t& r3, uint32_t addr)
{
    asm volatile("ldmatrix.sync.aligned.m8n8.x4.trans.shared.b16 {%0,%1,%2,%3}, [%4];"
                 : "=r"(r0), "=r"(r1), "=r"(r2), "=r"(r3) : "r"(addr));
}

__device__ __forceinline__ float gelu_fn(float x) {
    const float c = 0.7978845608028654f;
    float x3 = x * x * x;
    return 0.5f * x * (1.0f + tanhf(c * (x + 0.044715f * x3)));
}

// ---------------------------------------------------------------------------
// Prep kernels (fork-join: prep_b overlaps QKV GEMM + attention)
// ---------------------------------------------------------------------------
__device__ __forceinline__ void transpose_tile(
    float (*t)[33], const float* __restrict__ W, __half* __restrict__ Wt,
    int K, int N, int bx, int by, int tid)
{
    const int tx = tid & 31;
    const int ty = tid >> 5;
    const int b0 = bx * 32, k0 = by * 32;
#pragma unroll
    for (int q = 0; q < 4; q++)
        t[ty + q * 8][tx] = W[(size_t)(k0 + ty + q * 8) * N + b0 + tx];
    __syncthreads();
#pragma unroll
    for (int q = 0; q < 4; q++)
        Wt[(size_t)(b0 + ty + q * 8) * K + k0 + tx] = __float2half_rn(t[tx][ty + q * 8]);
}

__global__ void __launch_bounds__(256) prep_a_kernel(
    const float* __restrict__ Wq, const float* __restrict__ Wk,
    const float* __restrict__ Wv, const float* __restrict__ x,
    const float* __restrict__ bq, const float* __restrict__ bk,
    const float* __restrict__ bv)
{
    __shared__ float t[32][33];
    const int id  = blockIdx.x;
    const int tid = threadIdx.x;

    if (id < 3072) {
        const int m = id >> 10;
        const float* W = (m == 0) ? Wq : (m == 1) ? Wk : Wv;
        __half* Wt = g_wqkvt + (size_t)m * HID * HID;
        const int lid = id & 1023;
        transpose_tile(t, W, Wt, HID, HID, lid & 31, lid >> 5, tid);
    } else if (id < 7168) {
        const int i = ((id - 3072) * 256 + tid) * 8;
        float4 a = *(const float4*)&x[i];
        float4 b = *(const float4*)&x[i + 4];
        __half2 h[4];
        h[0] = __floats2half2_rn(a.x, a.y);
        h[1] = __floats2half2_rn(a.z, a.w);
        h[2] = __floats2half2_rn(b.x, b.y);
        h[3] = __floats2half2_rn(b.z, b.w);
        *(uint4*)&g_xh[i] = *(uint4*)h;
    } else {
        const int i = (id - 7168) * 256 + tid;       // 0..3071
        const int seg = i >> 10, off = i & 1023;
        g_bqkv[i] = (seg == 0) ? bq[off] : (seg == 1) ? bk[off] : bv[off];
    }
}

__global__ void __launch_bounds__(256) prep_b_kernel(
    const float* __restrict__ Wo, const float* __restrict__ W1,
    const float* __restrict__ W2)
{
    __shared__ float t[32][33];
    const int id  = blockIdx.x;
    const int tid = threadIdx.x;

    if (id < 1024) {
        transpose_tile(t, Wo, g_wot, HID, HID, id & 31, id >> 5, tid);
    } else if (id < 5120) {
        const int lid = id - 1024;
        transpose_tile(t, W1, g_w1t, HID, DFF, lid & 127, lid >> 7, tid);
    } else {
        const int lid = id - 5120;
        transpose_tile(t, W2, g_w2t, DFF, HID, lid & 31, lid >> 5, tid);
    }
}

// ---------------------------------------------------------------------------
// fp16 mma.sync GEMM (proven config): CTA 128x128, BK=64, 2-stage cp.async,
// 8 warps (4m x 2n), warp 32x64, 2 CTAs/SM.
// EPI: 1 = half out, 2 = half out + GELU, 3 = half out, cols<HID scaled 0.125
// ---------------------------------------------------------------------------
#define HPAD 72
#define BM 128
#define BN 128
#define STAGE_H ((BM + BN) * HPAD)
#define GEMM_SMEM (2 * STAGE_H * 2)                    // 73728 bytes

__device__ __forceinline__ void fill_stage(
    __half* As, __half* Bs, const __half* A, const __half* Bt,
    int bm, int bn, int k0, int K, int tid)
{
#pragma unroll
    for (int q = 0; q < 4; q++) {
        int idx = q * 256 + tid;
        int row = idx >> 3, c = idx & 7;
        cp_async16(smem_u32(&As[row * HPAD + c * 8]),
                   &A[(size_t)(bm + row) * K + k0 + c * 8]);
    }
#pragma unroll
    for (int q = 0; q < 4; q++) {
        int idx = q * 256 + tid;
        int row = idx >> 3, c = idx & 7;
        cp_async16(smem_u32(&Bs[row * HPAD + c * 8]),
                   &Bt[(size_t)(bn + row) * K + k0 + c * 8]);
    }
}

template<int EPI>
__global__ void __launch_bounds__(256, 2) mma_gemm_h(
    const __half* __restrict__ A, const __half* __restrict__ Bt,
    const float* __restrict__ bias, __half* __restrict__ C,
    int M, int N, int K)
{
    extern __shared__ __half shh[];
    const int tid  = threadIdx.x;
    const int wid  = tid >> 5;
    const int lane = tid & 31;
    const int g    = lane >> 2;
    const int t    = lane & 3;
    const int bm   = blockIdx.y * BM;
    const int bn   = blockIdx.x * BN;
    const int moff = (wid & 3) * 32;
    const int noff = (wid >> 2) * 64;

    const int a_r = lane & 15;
    const int a_c = (lane >> 4) * 8;
    const int b_r = (lane & 7) + ((lane >> 4) << 3);
    const int b_c = ((lane >> 3) & 1) * 8;

    const int iters = K >> 6;

    float acc[2][8][4];
#pragma unroll
    for (int a = 0; a < 2; a++)
#pragma unroll
        for (int b = 0; b < 8; b++)
#pragma unroll
            for (int c = 0; c < 4; c++) acc[a][b][c] = 0.0f;

    fill_stage(shh, shh + BM * HPAD, A, Bt, bm, bn, 0, K, tid);
    CP_COMMIT();

    for (int i = 0; i < iters; i++) {
        CP_WAIT(0);
        __syncthreads();

        if (i + 1 < iters) {
            __half* st = shh + ((i + 1) & 1) * STAGE_H;
            fill_stage(st, st + BM * HPAD, A, Bt, bm, bn, (i + 1) * 64, K, tid);
            CP_COMMIT();
        }

        const __half* As = shh + (i & 1) * STAGE_H;
        const __half* Bs = As + BM * HPAD;
#pragma unroll
        for (int ks = 0; ks < 4; ks++) {
            uint32_t af[2][4], bf[8][2];
#pragma unroll
            for (int mt = 0; mt < 2; mt++) {
                uint32_t addr = smem_u32(
                    &As[(moff + mt * 16 + a_r) * HPAD + ks * 16 + a_c]);
                ldmatrix_x4(af[mt][0], af[mt][1], af[mt][2], af[mt][3], addr);
            }
#pragma unroll
            for (int np = 0; np < 4; np++) {
                uint32_t addr = smem_u32(
                    &Bs[(noff + np * 16 + b_r) * HPAD + ks * 16 + b_c]);
                ldmatrix_x4(bf[np * 2][0], bf[np * 2][1],
                            bf[np * 2 + 1][0], bf[np * 2 + 1][1], addr);
            }
#pragma unroll
            for (int mt = 0; mt < 2; mt++)
#pragma unroll
                for (int nt = 0; nt < 8; nt++)
                    mma_f16(acc[mt][nt][0], acc[mt][nt][1], acc[mt][nt][2], acc[mt][nt][3],
                            af[mt][0], af[mt][1], af[mt][2], af[mt][3],
                            bf[nt][0], bf[nt][1]);
        }
        __syncthreads();
    }

    // epilogue (half out)
#pragma unroll
    for (int nt = 0; nt < 8; nt++) {
        const int col = bn + noff + nt * 8 + 2 * t;
        const float2 bv = *(const float2*)&bias[col];
        const float sc = (EPI == 3 && col < HID) ? 0.125f : 1.0f;
#pragma unroll
        for (int mt = 0; mt < 2; mt++) {
            const int r0 = bm + moff + mt * 16 + g;
            float c0 = acc[mt][nt][0] + bv.x;
            float c1 = acc[mt][nt][1] + bv.y;
            float c2 = acc[mt][nt][2] + bv.x;
            float c3 = acc[mt][nt][3] + bv.y;
            if (EPI == 2) {
                c0 = gelu_fn(c0); c1 = gelu_fn(c1);
                c2 = gelu_fn(c2); c3 = gelu_fn(c3);
            }
            if (EPI == 3) { c0 *= sc; c1 *= sc; c2 *= sc; c3 *= sc; }
            *(__half2*)&C[(size_t)r0 * N + col]       = __floats2half2_rn(c0, c1);
            *(__half2*)&C[(size_t)(r0 + 8) * N + col] = __floats2half2_rn(c2, c3);
        }
    }
}

// ---------------------------------------------------------------------------
// Flash attention. Q pre-scaled by 0.125. QK^T uses fp16-accumulator mma
// (K=64 accumulation depth -> safe); PV keeps fp32 accumulators.
// ---------------------------------------------------------------------------
#define BQ   128
#define BKV  64
#define NKB  (SEQ / BKV)
#define ATT_SMEM ((2 * BQ * HPAD + 4 * BKV * HPAD) * 2)   // 73728 B

__global__ void __launch_bounds__(256, 2) attn_mma_h_kernel(
    const __half* __restrict__ QKV, __half* __restrict__ Og)
{
    extern __shared__ __half sha[];
    __half* Qs = sha;
    __half* Ks = sha + BQ * HPAD;
    __half* Vs = sha + BQ * HPAD + 2 * BKV * HPAD;
    __half* Ps = sha + BQ * HPAD + 4 * BKV * HPAD;

    const int tid  = threadIdx.x;
    const int wid  = tid >> 5;
    const int lane = tid & 31;
    const int g    = lane >> 2;
    const int t    = lane & 3;
    const int qt   = blockIdx.x;
    const int head = blockIdx.y;
    const int b    = blockIdx.z;

    const size_t baseq = ((size_t)b * SEQ) * NQKV + (size_t)head * DK;
    const __half* Qg = QKV + baseq;
    const __half* Kg = QKV + baseq + HID;
    const __half* Vg = QKV + baseq + 2 * HID;
    const size_t baso = ((size_t)b * SEQ) * HID + (size_t)head * DK;

    const int q0   = qt * BQ;
    const int moff = wid * 16;

    const int a_r = lane & 15;
    const int a_c = (lane >> 4) * 8;
    const int b_r = (lane & 7) + ((lane >> 4) << 3);
    const int b_c = ((lane >> 3) & 1) * 8;

#pragma unroll
    for (int q = 0; q < 4; q++) {
        int idx = q * 256 + tid;
        int r = idx >> 3, c = idx & 7;
        cp_async16(smem_u32(&Qs[r * HPAD + c * 8]),
                   &Qg[(size_t)(q0 + r) * NQKV + c * 8]);
    }
#pragma unroll
    for (int q = 0; q < 2; q++) {
        int idx = q * 256 + tid;
        int r = idx >> 3, c = idx & 7;
        cp_async16(smem_u32(&Ks[r * HPAD + c * 8]),
                   &Kg[(size_t)r * NQKV + c * 8]);
        cp_async16(smem_u32(&Vs[r * HPAD + c * 8]),
                   &Vg[(size_t)r * NQKV + c * 8]);
    }
    CP_COMMIT();

    const uint32_t vlane_off = (uint32_t)((lane & 15) * HPAD + (lane >> 4) * 8);

    float oacc[8][4];
#pragma unroll
    for (int nt = 0; nt < 8; nt++)
#pragma unroll
        for (int c = 0; c < 4; c++) oacc[nt][c] = 0.0f;
    float m0 = -1e30f, m1 = -1e30f, l0 = 0.0f, l1 = 0.0f;

    for (int i = 0; i < NKB; i++) {
        if (i + 1 < NKB) {
            const int kn = (i + 1) * BKV;
            __half* Kb = Ks + ((i + 1) & 1) * BKV * HPAD;
            __half* Vb = Vs + ((i + 1) & 1) * BKV * HPAD;
#pragma unroll
            for (int q = 0; q < 2; q++) {
                int idx = q * 256 + tid;
                int r = idx >> 3, c = idx & 7;
                cp_async16(smem_u32(&Kb[r * HPAD + c * 8]),
                           &Kg[(size_t)(kn + r) * NQKV + c * 8]);
                cp_async16(smem_u32(&Vb[r * HPAD + c * 8]),
                           &Vg[(size_t)(kn + r) * NQKV + c * 8]);
            }
            CP_COMMIT();
            CP_WAIT(1);
        } else {
            CP_WAIT(0);
        }
        __syncthreads();

        const __half* Kb = Ks + (i & 1) * BKV * HPAD;
        const __half* Vb = Vs + (i & 1) * BKV * HPAD;

        // ---- S = Q K^T  (fp16 accumulators, K-depth 64) ----
        uint32_t sh_[8][2];
#pragma unroll
        for (int nt = 0; nt < 8; nt++) { sh_[nt][0] = 0u; sh_[nt][1] = 0u; }

#pragma unroll
        for (int ks = 0; ks < 4; ks++) {
            uint32_t qf[4];
            {
                uint32_t addr = smem_u32(
                    &Qs[(moff + a_r) * HPAD + ks * 16 + a_c]);
                ldmatrix_x4(qf[0], qf[1], qf[2], qf[3], addr);
            }
            uint32_t bf[8][2];
#pragma unroll
            for (int np = 0; np < 4; np++) {
                uint32_t addr = smem_u32(
                    &Kb[(np * 16 + b_r) * HPAD + ks * 16 + b_c]);
                ldmatrix_x4(bf[np * 2][0], bf[np * 2][1],
                            bf[np * 2 + 1][0], bf[np * 2 + 1][1], addr);
            }
#pragma unroll
            for (int nt = 0; nt < 8; nt++)
                mma_f16acc(sh_[nt][0], sh_[nt][1],
                           qf[0], qf[1], qf[2], qf[3],
                           bf[nt][0], bf[nt][1]);
        }

        // convert fp16 scores -> fp32
        float sacc[8][4];
#pragma unroll
        for (int nt = 0; nt < 8; nt++) {
            float2 p0 = __half22float2(*(__half2*)&sh_[nt][0]);
            float2 p1 = __half22float2(*(__half2*)&sh_[nt][1]);
            sacc[nt][0] = p0.x; sacc[nt][1] = p0.y;
            sacc[nt][2] = p1.x; sacc[nt][3] = p1.y;
        }

        // online softmax (Q carried the 1/8 scale)
        float rx0 = -1e30f, rx1 = -1e30f;
#pragma unroll
        for (int nt = 0; nt < 8; nt++) {
            rx0 = fmaxf(rx0, fmaxf(sacc[nt][0], sacc[nt][1]));
            rx1 = fmaxf(rx1, fmaxf(sacc[nt][2], sacc[nt][3]));
        }
        rx0 = fmaxf(rx0, __shfl_xor_sync(0xffffffffu, rx0, 1));
        rx0 = fmaxf(rx0, __shfl_xor_sync(0xffffffffu, rx0, 2));
        rx1 = fmaxf(rx1, __shfl_xor_sync(0xffffffffu, rx1, 1));
        rx1 = fmaxf(rx1, __shfl_xor_sync(0xffffffffu, rx1, 2));

        const float nm0 = fmaxf(m0, rx0);
        const float nm1 = fmaxf(m1, rx1);
        const float corr0 = __expf(m0 - nm0);
        const float corr1 = __expf(m1 - nm1);

        float rs0 = 0.0f, rs1 = 0.0f;
#pragma unroll
        for (int nt = 0; nt < 8; nt++) {
            sacc[nt][0] = __expf(sacc[nt][0] - nm0);
            sacc[nt][1] = __expf(sacc[nt][1] - nm0);
            sacc[nt][2] = __expf(sacc[nt][2] - nm1);
            sacc[nt][3] = __expf(sacc[nt][3] - nm1);
            rs0 += sacc[nt][0] + sacc[nt][1];
            rs1 += sacc[nt][2] + sacc[nt][3];
        }
        rs0 += __shfl_xor_sync(0xffffffffu, rs0, 1);
        rs0 += __shfl_xor_sync(0xffffffffu, rs0, 2);
        rs1 += __shfl_xor_sync(0xffffffffu, rs1, 1);
        rs1 += __shfl_xor_sync(0xffffffffu, rs1, 2);

        l0 = l0 * corr0 + rs0;  m0 = nm0;
        l1 = l1 * corr1 + rs1;  m1 = nm1;

#pragma unroll
        for (int nt = 0; nt < 8; nt++) {
            oacc[nt][0] *= corr0; oacc[nt][1] *= corr0;
            oacc[nt][2] *= corr1; oacc[nt][3] *= corr1;
        }

#pragma unroll
        for (int nt = 0; nt < 8; nt++) {
            *(__half2*)&Ps[(moff + g) * HPAD + nt * 8 + 2 * t] =
                __floats2half2_rn(sacc[nt][0], sacc[nt][1]);
            *(__half2*)&Ps[(moff + 8 + g) * HPAD + nt * 8 + 2 * t] =
                __floats2half2_rn(sacc[nt][2], sacc[nt][3]);
        }
        __syncwarp();

        // ---- O += P @ V  (fp32 accumulators) ----
        const uint32_t vbase = smem_u32(Vb) + vlane_off * 2;
#pragma unroll
        for (int ks = 0; ks < 4; ks++) {
            const int kc = ks * 16 + 2 * t;
            const uint32_t a0 = *(const uint32_t*)&Ps[(moff + g) * HPAD + kc];
            const uint32_t a1 = *(const uint32_t*)&Ps[(moff + 8 + g) * HPAD + kc];
            const uint32_t a2 = *(const uint32_t*)&Ps[(moff + g) * HPAD + kc + 8];
            const uint32_t a3 = *(const uint32_t*)&Ps[(moff + 8 + g) * HPAD + kc + 8];
            const uint32_t vrow = vbase + (uint32_t)(ks * 16 * HPAD * 2);
#pragma unroll
            for (int n16 = 0; n16 < 4; n16++) {
                uint32_t r0, r1, r2, r3;
                ldmatrix_x4_trans(r0, r1, r2, r3, vrow + (uint32_t)(n16 * 32));
                mma_f16(oacc[n16 * 2][0], oacc[n16 * 2][1], oacc[n16 * 2][2], oacc[n16 * 2][3],
                        a0, a1, a2, a3, r0, r1);
                mma_f16(oacc[n16 * 2 + 1][0], oacc[n16 * 2 + 1][1],
                        oacc[n16 * 2 + 1][2], oacc[n16 * 2 + 1][3],
                        a0, a1, a2, a3, r2, r3);
            }
        }
        __syncthreads();
    }

    const float inv0 = 1.0f / l0;
    const float inv1 = 1.0f / l1;
    const int r0 = q0 + moff + g;
    const int r1 = r0 + 8;
#pragma unroll
    for (int nt = 0; nt < 8; nt++) {
        const int col = nt * 8 + 2 * t;
        *(__half2*)&Og[baso + (size_t)r0 * HID + col] =
            __floats2half2_rn(oacc[nt][0] * inv0, oacc[nt][1] * inv0);
        *(__half2*)&Og[baso + (size_t)r1 * HID + col] =
            __floats2half2_rn(oacc[nt][2] * inv1, oacc[nt][3] * inv1);
    }
}

// ---------------------------------------------------------------------------
// Residual add + LayerNorm.  X fp32, Y fp16.  Optionally emits a half copy.
// ---------------------------------------------------------------------------
template<int HALF_OUT>
__global__ void __launch_bounds__(256) add_ln_kernel(
    const float* __restrict__ X, const __half* __restrict__ Y,
    const float* __restrict__ g, const float* __restrict__ be,
    float* __restrict__ out, __half* __restrict__ outh)
{
    const int row = blockIdx.x;
    const int tid = threadIdx.x;
    const size_t base = (size_t)row * HID;

    float v[4];
    float s = 0.0f, s2 = 0.0f;
#pragma unroll
    for (int k = 0; k < 4; k++) {
        int c = tid + k * 256;
        float tt = X[base + c] + __half2float(Y[base + c]);
        v[k] = tt;
        s += tt;
        s2 += tt * tt;
    }
#pragma unroll
    for (int off = 16; off > 0; off >>= 1) {
        s  += __shfl_xor_sync(0xffffffffu, s,  off);
        s2 += __shfl_xor_sync(0xffffffffu, s2, off);
    }
    __shared__ float red[16];
    const int warp = tid >> 5, lane = tid & 31;
    if (lane == 0) { red[warp] = s; red[warp + 8] = s2; }
    __syncthreads();
    if (tid < 32) {
        float a = (lane < 8) ? red[lane]     : 0.0f;
        float c2 = (lane < 8) ? red[lane + 8] : 0.0f;
#pragma unroll
        for (int off = 4; off > 0; off >>= 1) {
            a  += __shfl_xor_sync(0xffffffffu, a,  off);
            c2 += __shfl_xor_sync(0xffffffffu, c2, off);
        }
        if (lane == 0) { red[0] = a; red[1] = c2; }
    }
    __syncthreads();
    const float mu  = red[0] * (1.0f / HID);
    const float var = red[1] * (1.0f / HID) - mu * mu;
    const float inv = rsqrtf(var + 1e-5f);
#pragma unroll
    for (int k = 0; k < 4; k++) {
        int c = tid + k * 256;
        float r = (v[k] - mu) * inv * g[c] + be[c];
        out[base + c] = r;
        if (HALF_OUT) outh[base + c] = __float2half_rn(r);
    }
}

// ---------------------------------------------------------------------------
// kernel_launch
// ---------------------------------------------------------------------------
extern "C" void kernel_launch(void* const* d_in, const int* in_sizes, int n_in,
                              void* d_out, int out_size)
{
    const float* x  = (const float*)d_in[0];
    const float* Wq = (const float*)d_in[1];
    const float* bq = (const float*)d_in[2];
    const float* Wk = (const float*)d_in[3];
    const float* bk = (const float*)d_in[4];
    const float* Wv = (const float*)d_in[5];
    const float* bv = (const float*)d_in[6];
    const float* Wo = (const float*)d_in[7];
    const float* bo = (const float*)d_in[8];
    const float* W1 = (const float*)d_in[9];
    const float* b1 = (const float*)d_in[10];
    const float* W2 = (const float*)d_in[11];
    const float* b2 = (const float*)d_in[12];
    const float* g1 = (const float*)d_in[13];
    const float* be1= (const float*)d_in[14];
    const float* g2 = (const float*)d_in[15];
    const float* be2= (const float*)d_in[16];
    float* out = (float*)d_out;

    __half *xh, *qkvh, *ctxh, *aoh, *x1h, *hh, *ffh;
    float *x1, *bqkv;
    __half *wqkvt, *wot, *w1t, *w2t;
    cudaGetSymbolAddress((void**)&xh,    g_xh);
    cudaGetSymbolAddress((void**)&qkvh,  g_qkvh);
    cudaGetSymbolAddress((void**)&ctxh,  g_ctxh);
    cudaGetSymbolAddress((void**)&aoh,   g_aoh);
    cudaGetSymbolAddress((void**)&x1,    g_x1);
    cudaGetSymbolAddress((void**)&x1h,   g_x1h);
    cudaGetSymbolAddress((void**)&hh,    g_hh);
    cudaGetSymbolAddress((void**)&ffh,   g_ffh);
    cudaGetSymbolAddress((void**)&wqkvt, g_wqkvt);
    cudaGetSymbolAddress((void**)&wot,   g_wot);
    cudaGetSymbolAddress((void**)&w1t,   g_w1t);
    cudaGetSymbolAddress((void**)&w2t,   g_w2t);
    cudaGetSymbolAddress((void**)&bqkv,  g_bqkv);

    cudaFuncSetAttribute(attn_mma_h_kernel,
                         cudaFuncAttributeMaxDynamicSharedMemorySize, ATT_SMEM);
    cudaFuncSetAttribute(mma_gemm_h<1>,
                         cudaFuncAttributeMaxDynamicSharedMemorySize, GEMM_SMEM);
    cudaFuncSetAttribute(mma_gemm_h<2>,
                         cudaFuncAttributeMaxDynamicSharedMemorySize, GEMM_SMEM);
    cudaFuncSetAttribute(mma_gemm_h<3>,
                         cudaFuncAttributeMaxDynamicSharedMemorySize, GEMM_SMEM);

    const dim3 blk256(256);

    // fork: side stream for Wo/W1/W2 prep (overlaps QKV GEMM + attention)
    cudaStream_t s1;
    cudaEvent_t evFork, evJoin;
    cudaStreamCreateWithFlags(&s1, cudaStreamNonBlocking);
    cudaEventCreateWithFlags(&evFork, cudaEventDisableTiming);
    cudaEventCreateWithFlags(&evJoin, cudaEventDisableTiming);

    cudaEventRecord(evFork, 0);
    cudaStreamWaitEvent(s1, evFork, 0);
    prep_b_kernel<<<9216, blk256, 0, s1>>>(Wo, W1, W2);
    cudaEventRecord(evJoin, s1);

    // main stream: QKV path
    prep_a_kernel<<<7180, blk256>>>(Wq, Wk, Wv, x, bq, bk, bv);

    // fused QKV GEMM (Q columns pre-scaled by 0.125)
    mma_gemm_h<3><<<dim3(NQKV / BN, MTOT / BM), blk256, GEMM_SMEM>>>(
        xh, wqkvt, bqkv, qkvh, MTOT, NQKV, HID);

    // attention
    attn_mma_h_kernel<<<dim3(SEQ / BQ, NHEAD, BATCH), blk256, ATT_SMEM>>>(qkvh, ctxh);

    // join: Wo/W1/W2 weights must be ready from here on
    cudaStreamWaitEvent(0, evJoin, 0);

    const dim3 gProj(HID / BN, MTOT / BM);   // (8, 64)
    const dim3 gFF1 (DFF / BN, MTOT / BM);   // (32, 64)

    // output projection (half out) + residual/LN1 (fp32 + half copies)
    mma_gemm_h<1><<<gProj, blk256, GEMM_SMEM>>>(ctxh, wot, bo, aoh, MTOT, HID, HID);
    add_ln_kernel<1><<<MTOT, blk256>>>(x, aoh, g1, be1, x1, x1h);

    // FFN
    mma_gemm_h<2><<<gFF1, blk256, GEMM_SMEM>>>(x1h, w1t, b1, hh, MTOT, DFF, HID);
    mma_gemm_h<1><<<gProj, blk256, GEMM_SMEM>>>(hh, w2t, b2, ffh, MTOT, HID, DFF);

    // residual/LN2 -> output
    add_ln_kernel<0><<<MTOT, blk256>>>(x1, ffh, g2, be2, out, nullptr);
}

// round 17
// speedup vs baseline: 1.0332x; 1.0332x over previous
#include <cuda_runtime.h>
#include <cuda_fp16.h>
#include <math.h>
#include <cstdint>

// Problem constants
#define BATCH 4
#define SEQ   2048
#define HID   1024
#define NHEAD 16
#define DK    64
#define DFF   4096
#define MTOT  (BATCH * SEQ)          // 8192 rows
#define NQKV  (3 * HID)              // 3072

// ---------------------------------------------------------------------------
// Scratch
// ---------------------------------------------------------------------------
__device__ __half g_xh  [MTOT * HID];
__device__ __half g_qkvh[MTOT * NQKV];
__device__ __half g_ctxh[MTOT * HID];
__device__ __half g_aoh [MTOT * HID];
__device__ float  g_x1  [MTOT * HID];
__device__ __half g_x1h [MTOT * HID];
__device__ __half g_hh  [MTOT * DFF];
__device__ __half g_ffh [MTOT * HID];
__device__ __half g_wqkvt[NQKV * HID];
__device__ __half g_wot [HID * HID];
__device__ __half g_w1t [HID * DFF];
__device__ __half g_w2t [DFF * HID];
__device__ float  g_bqkv[NQKV];

// ---------------------------------------------------------------------------
// helpers
// ---------------------------------------------------------------------------
__device__ __forceinline__ uint32_t smem_u32(const void* p) {
    uint32_t a;
    asm("{ .reg .u64 t; cvta.to.shared.u64 t, %1; cvt.u32.u64 %0, t; }" : "=r"(a) : "l"(p));
    return a;
}
__device__ __forceinline__ void cp_async16(uint32_t saddr, const void* gaddr) {
    asm volatile("cp.async.cg.shared.global [%0], [%1], 16;" :: "r"(saddr), "l"(gaddr) : "memory");
}
#define CP_COMMIT() asm volatile("cp.async.commit_group;" ::: "memory")
#define CP_WAIT(n)  asm volatile("cp.async.wait_group %0;" :: "n"(n) : "memory")

__device__ __forceinline__ uint32_t pack_h2(float lo, float hi) {
    __half2 h = __floats2half2_rn(lo, hi);
    return *(uint32_t*)&h;
}

__device__ __forceinline__ void mma_f16(
    float& d0, float& d1, float& d2, float& d3,
    uint32_t a0, uint32_t a1, uint32_t a2, uint32_t a3,
    uint32_t b0, uint32_t b1)
{
    asm volatile(
        "mma.sync.aligned.m16n8k16.row.col.f32.f16.f16.f32 "
        "{%0,%1,%2,%3}, {%4,%5,%6,%7}, {%8,%9}, {%0,%1,%2,%3};"
        : "+f"(d0), "+f"(d1), "+f"(d2), "+f"(d3)
        : "r"(a0), "r"(a1), "r"(a2), "r"(a3), "r"(b0), "r"(b1));
}
__device__ __forceinline__ void ldmatrix_x4(
    uint32_t& r0, uint32_t& r1, uint32_t& r2, uint32_t& r3, uint32_t addr)
{
    asm volatile("ldmatrix.sync.aligned.m8n8.x4.shared.b16 {%0,%1,%2,%3}, [%4];"
                 : "=r"(r0), "=r"(r1), "=r"(r2), "=r"(r3) : "r"(addr));
}
__device__ __forceinline__ void ldmatrix_x4_trans(
    uint32_t& r0, uint32_t& r1, uint32_t& r2, uint32_t& r3, uint32_t addr)
{
    asm volatile("ldmatrix.sync.aligned.m8n8.x4.trans.shared.b16 {%0,%1,%2,%3}, [%4];"
                 : "=r"(r0), "=r"(r1), "=r"(r2), "=r"(r3) : "r"(addr));
}

__device__ __forceinline__ float gelu_fn(float x) {
    const float c = 0.7978845608028654f;
    float x3 = x * x * x;
    return 0.5f * x * (1.0f + tanhf(c * (x + 0.044715f * x3)));
}

// ---------------------------------------------------------------------------
// Prep kernels (fork-join: prep_b overlaps QKV GEMM + attention)
// ---------------------------------------------------------------------------
__device__ __forceinline__ void transpose_tile(
    float (*t)[33], const float* __restrict__ W, __half* __restrict__ Wt,
    int K, int N, int bx, int by, int tid)
{
    const int tx = tid & 31;
    const int ty = tid >> 5;
    const int b0 = bx * 32, k0 = by * 32;
#pragma unroll
    for (int q = 0; q < 4; q++)
        t[ty + q * 8][tx] = W[(size_t)(k0 + ty + q * 8) * N + b0 + tx];
    __syncthreads();
#pragma unroll
    for (int q = 0; q < 4; q++)
        Wt[(size_t)(b0 + ty + q * 8) * K + k0 + tx] = __float2half_rn(t[tx][ty + q * 8]);
}

__global__ void __launch_bounds__(256) prep_a_kernel(
    const float* __restrict__ Wq, const float* __restrict__ Wk,
    const float* __restrict__ Wv, const float* __restrict__ x,
    const float* __restrict__ bq, const float* __restrict__ bk,
    const float* __restrict__ bv)
{
    __shared__ float t[32][33];
    const int id  = blockIdx.x;
    const int tid = threadIdx.x;

    if (id < 3072) {
        const int m = id >> 10;
        const float* W = (m == 0) ? Wq : (m == 1) ? Wk : Wv;
        __half* Wt = g_wqkvt + (size_t)m * HID * HID;
        const int lid = id & 1023;
        transpose_tile(t, W, Wt, HID, HID, lid & 31, lid >> 5, tid);
    } else if (id < 7168) {
        const int i = ((id - 3072) * 256 + tid) * 8;
        float4 a = *(const float4*)&x[i];
        float4 b = *(const float4*)&x[i + 4];
        __half2 h[4];
        h[0] = __floats2half2_rn(a.x, a.y);
        h[1] = __floats2half2_rn(a.z, a.w);
        h[2] = __floats2half2_rn(b.x, b.y);
        h[3] = __floats2half2_rn(b.z, b.w);
        *(uint4*)&g_xh[i] = *(uint4*)h;
    } else {
        const int i = (id - 7168) * 256 + tid;       // 0..3071
        const int seg = i >> 10, off = i & 1023;
        g_bqkv[i] = (seg == 0) ? bq[off] : (seg == 1) ? bk[off] : bv[off];
    }
}

__global__ void __launch_bounds__(256) prep_b_kernel(
    const float* __restrict__ Wo, const float* __restrict__ W1,
    const float* __restrict__ W2)
{
    __shared__ float t[32][33];
    const int id  = blockIdx.x;
    const int tid = threadIdx.x;

    if (id < 1024) {
        transpose_tile(t, Wo, g_wot, HID, HID, id & 31, id >> 5, tid);
    } else if (id < 5120) {
        const int lid = id - 1024;
        transpose_tile(t, W1, g_w1t, HID, DFF, lid & 127, lid >> 7, tid);
    } else {
        const int lid = id - 5120;
        transpose_tile(t, W2, g_w2t, DFF, HID, lid & 31, lid >> 5, tid);
    }
}

// ---------------------------------------------------------------------------
// fp16 mma.sync GEMM (proven config): CTA 128x128, BK=64, 2-stage cp.async,
// 8 warps (4m x 2n), warp 32x64, 2 CTAs/SM.
// EPI: 1 = half out, 2 = half out + GELU, 3 = half out, cols<HID scaled 0.125
// ---------------------------------------------------------------------------
#define HPAD 72
#define BM 128
#define BN 128
#define STAGE_H ((BM + BN) * HPAD)
#define GEMM_SMEM (2 * STAGE_H * 2)                    // 73728 bytes

__device__ __forceinline__ void fill_stage(
    __half* As, __half* Bs, const __half* A, const __half* Bt,
    int bm, int bn, int k0, int K, int tid)
{
#pragma unroll
    for (int q = 0; q < 4; q++) {
        int idx = q * 256 + tid;
        int row = idx >> 3, c = idx & 7;
        cp_async16(smem_u32(&As[row * HPAD + c * 8]),
                   &A[(size_t)(bm + row) * K + k0 + c * 8]);
    }
#pragma unroll
    for (int q = 0; q < 4; q++) {
        int idx = q * 256 + tid;
        int row = idx >> 3, c = idx & 7;
        cp_async16(smem_u32(&Bs[row * HPAD + c * 8]),
                   &Bt[(size_t)(bn + row) * K + k0 + c * 8]);
    }
}

template<int EPI>
__global__ void __launch_bounds__(256, 2) mma_gemm_h(
    const __half* __restrict__ A, const __half* __restrict__ Bt,
    const float* __restrict__ bias, __half* __restrict__ C,
    int M, int N, int K)
{
    extern __shared__ __half shh[];
    const int tid  = threadIdx.x;
    const int wid  = tid >> 5;
    const int lane = tid & 31;
    const int g    = lane >> 2;
    const int t    = lane & 3;
    const int bm   = blockIdx.y * BM;
    const int bn   = blockIdx.x * BN;
    const int moff = (wid & 3) * 32;
    const int noff = (wid >> 2) * 64;

    const int a_r = lane & 15;
    const int a_c = (lane >> 4) * 8;
    const int b_r = (lane & 7) + ((lane >> 4) << 3);
    const int b_c = ((lane >> 3) & 1) * 8;

    const int iters = K >> 6;

    float acc[2][8][4];
#pragma unroll
    for (int a = 0; a < 2; a++)
#pragma unroll
        for (int b = 0; b < 8; b++)
#pragma unroll
            for (int c = 0; c < 4; c++) acc[a][b][c] = 0.0f;

    fill_stage(shh, shh + BM * HPAD, A, Bt, bm, bn, 0, K, tid);
    CP_COMMIT();

    for (int i = 0; i < iters; i++) {
        CP_WAIT(0);
        __syncthreads();

        if (i + 1 < iters) {
            __half* st = shh + ((i + 1) & 1) * STAGE_H;
            fill_stage(st, st + BM * HPAD, A, Bt, bm, bn, (i + 1) * 64, K, tid);
            CP_COMMIT();
        }

        const __half* As = shh + (i & 1) * STAGE_H;
        const __half* Bs = As + BM * HPAD;
#pragma unroll
        for (int ks = 0; ks < 4; ks++) {
            uint32_t af[2][4], bf[8][2];
#pragma unroll
            for (int mt = 0; mt < 2; mt++) {
                uint32_t addr = smem_u32(
                    &As[(moff + mt * 16 + a_r) * HPAD + ks * 16 + a_c]);
                ldmatrix_x4(af[mt][0], af[mt][1], af[mt][2], af[mt][3], addr);
            }
#pragma unroll
            for (int np = 0; np < 4; np++) {
                uint32_t addr = smem_u32(
                    &Bs[(noff + np * 16 + b_r) * HPAD + ks * 16 + b_c]);
                ldmatrix_x4(bf[np * 2][0], bf[np * 2][1],
                            bf[np * 2 + 1][0], bf[np * 2 + 1][1], addr);
            }
#pragma unroll
            for (int mt = 0; mt < 2; mt++)
#pragma unroll
                for (int nt = 0; nt < 8; nt++)
                    mma_f16(acc[mt][nt][0], acc[mt][nt][1], acc[mt][nt][2], acc[mt][nt][3],
                            af[mt][0], af[mt][1], af[mt][2], af[mt][3],
                            bf[nt][0], bf[nt][1]);
        }
        __syncthreads();
    }

    // epilogue (half out)
#pragma unroll
    for (int nt = 0; nt < 8; nt++) {
        const int col = bn + noff + nt * 8 + 2 * t;
        const float2 bv = *(const float2*)&bias[col];
        const float sc = (EPI == 3 && col < HID) ? 0.125f : 1.0f;
#pragma unroll
        for (int mt = 0; mt < 2; mt++) {
            const int r0 = bm + moff + mt * 16 + g;
            float c0 = acc[mt][nt][0] + bv.x;
            float c1 = acc[mt][nt][1] + bv.y;
            float c2 = acc[mt][nt][2] + bv.x;
            float c3 = acc[mt][nt][3] + bv.y;
            if (EPI == 2) {
                c0 = gelu_fn(c0); c1 = gelu_fn(c1);
                c2 = gelu_fn(c2); c3 = gelu_fn(c3);
            }
            if (EPI == 3) { c0 *= sc; c1 *= sc; c2 *= sc; c3 *= sc; }
            *(__half2*)&C[(size_t)r0 * N + col]       = __floats2half2_rn(c0, c1);
            *(__half2*)&C[(size_t)(r0 + 8) * N + col] = __floats2half2_rn(c2, c3);
        }
    }
}

// ---------------------------------------------------------------------------
// Flash attention. Q pre-scaled by 0.125. fp32 score accumulators.
// P passes from QK^T accumulators to PV A-fragments entirely in registers
// (FA-2 layout identity) — no P smem tile, no extra syncs.
// ---------------------------------------------------------------------------
#define BQ   128
#define BKV  64
#define NKB  (SEQ / BKV)
#define ATT_SMEM ((BQ * HPAD + 4 * BKV * HPAD) * 2)    // 55296 B

__global__ void __launch_bounds__(256, 2) attn_mma_h_kernel(
    const __half* __restrict__ QKV, __half* __restrict__ Og)
{
    extern __shared__ __half sha[];
    __half* Qs = sha;                              // [BQ][HPAD]
    __half* Ks = sha + BQ * HPAD;                  // [2][BKV][HPAD]
    __half* Vs = sha + BQ * HPAD + 2 * BKV * HPAD; // [2][BKV][HPAD]

    const int tid  = threadIdx.x;
    const int wid  = tid >> 5;
    const int lane = tid & 31;
    const int g    = lane >> 2;
    const int t    = lane & 3;
    const int qt   = blockIdx.x;
    const int head = blockIdx.y;
    const int b    = blockIdx.z;

    const size_t baseq = ((size_t)b * SEQ) * NQKV + (size_t)head * DK;
    const __half* Qg = QKV + baseq;
    const __half* Kg = QKV + baseq + HID;
    const __half* Vg = QKV + baseq + 2 * HID;
    const size_t baso = ((size_t)b * SEQ) * HID + (size_t)head * DK;

    const int q0   = qt * BQ;
    const int moff = wid * 16;

    const int a_r = lane & 15;
    const int a_c = (lane >> 4) * 8;
    const int b_r = (lane & 7) + ((lane >> 4) << 3);
    const int b_c = ((lane >> 3) & 1) * 8;

#pragma unroll
    for (int q = 0; q < 4; q++) {
        int idx = q * 256 + tid;
        int r = idx >> 3, c = idx & 7;
        cp_async16(smem_u32(&Qs[r * HPAD + c * 8]),
                   &Qg[(size_t)(q0 + r) * NQKV + c * 8]);
    }
#pragma unroll
    for (int q = 0; q < 2; q++) {
        int idx = q * 256 + tid;
        int r = idx >> 3, c = idx & 7;
        cp_async16(smem_u32(&Ks[r * HPAD + c * 8]),
                   &Kg[(size_t)r * NQKV + c * 8]);
        cp_async16(smem_u32(&Vs[r * HPAD + c * 8]),
                   &Vg[(size_t)r * NQKV + c * 8]);
    }
    CP_COMMIT();

    const uint32_t vlane_off = (uint32_t)((lane & 15) * HPAD + (lane >> 4) * 8);

    float oacc[8][4];
#pragma unroll
    for (int nt = 0; nt < 8; nt++)
#pragma unroll
        for (int c = 0; c < 4; c++) oacc[nt][c] = 0.0f;
    float m0 = -1e30f, m1 = -1e30f, l0 = 0.0f, l1 = 0.0f;

    for (int i = 0; i < NKB; i++) {
        if (i + 1 < NKB) {
            const int kn = (i + 1) * BKV;
            __half* Kb = Ks + ((i + 1) & 1) * BKV * HPAD;
            __half* Vb = Vs + ((i + 1) & 1) * BKV * HPAD;
#pragma unroll
            for (int q = 0; q < 2; q++) {
                int idx = q * 256 + tid;
                int r = idx >> 3, c = idx & 7;
                cp_async16(smem_u32(&Kb[r * HPAD + c * 8]),
                           &Kg[(size_t)(kn + r) * NQKV + c * 8]);
                cp_async16(smem_u32(&Vb[r * HPAD + c * 8]),
                           &Vg[(size_t)(kn + r) * NQKV + c * 8]);
            }
            CP_COMMIT();
            CP_WAIT(1);
        } else {
            CP_WAIT(0);
        }
        __syncthreads();

        const __half* Kb = Ks + (i & 1) * BKV * HPAD;
        const __half* Vb = Vs + (i & 1) * BKV * HPAD;

        // ---- S = Q K^T  (fp32 accumulators) ----
        float sacc[8][4];
#pragma unroll
        for (int nt = 0; nt < 8; nt++)
#pragma unroll
            for (int c = 0; c < 4; c++) sacc[nt][c] = 0.0f;

#pragma unroll
        for (int ks = 0; ks < 4; ks++) {
            uint32_t qf[4];
            {
                uint32_t addr = smem_u32(
                    &Qs[(moff + a_r) * HPAD + ks * 16 + a_c]);
                ldmatrix_x4(qf[0], qf[1], qf[2], qf[3], addr);
            }
            uint32_t bf[8][2];
#pragma unroll
            for (int np = 0; np < 4; np++) {
                uint32_t addr = smem_u32(
                    &Kb[(np * 16 + b_r) * HPAD + ks * 16 + b_c]);
                ldmatrix_x4(bf[np * 2][0], bf[np * 2][1],
                            bf[np * 2 + 1][0], bf[np * 2 + 1][1], addr);
            }
#pragma unroll
            for (int nt = 0; nt < 8; nt++)
                mma_f16(sacc[nt][0], sacc[nt][1], sacc[nt][2], sacc[nt][3],
                        qf[0], qf[1], qf[2], qf[3],
                        bf[nt][0], bf[nt][1]);
        }

        // online softmax (Q carried the 1/8 scale)
        float rx0 = -1e30f, rx1 = -1e30f;
#pragma unroll
        for (int nt = 0; nt < 8; nt++) {
            rx0 = fmaxf(rx0, fmaxf(sacc[nt][0], sacc[nt][1]));
            rx1 = fmaxf(rx1, fmaxf(sacc[nt][2], sacc[nt][3]));
        }
        rx0 = fmaxf(rx0, __shfl_xor_sync(0xffffffffu, rx0, 1));
        rx0 = fmaxf(rx0, __shfl_xor_sync(0xffffffffu, rx0, 2));
        rx1 = fmaxf(rx1, __shfl_xor_sync(0xffffffffu, rx1, 1));
        rx1 = fmaxf(rx1, __shfl_xor_sync(0xffffffffu, rx1, 2));

        const float nm0 = fmaxf(m0, rx0);
        const float nm1 = fmaxf(m1, rx1);
        const float corr0 = __expf(m0 - nm0);
        const float corr1 = __expf(m1 - nm1);

        float rs0 = 0.0f, rs1 = 0.0f;
#pragma unroll
        for (int nt = 0; nt < 8; nt++) {
            sacc[nt][0] = __expf(sacc[nt][0] - nm0);
            sacc[nt][1] = __expf(sacc[nt][1] - nm0);
            sacc[nt][2] = __expf(sacc[nt][2] - nm1);
            sacc[nt][3] = __expf(sacc[nt][3] - nm1);
            rs0 += sacc[nt][0] + sacc[nt][1];
            rs1 += sacc[nt][2] + sacc[nt][3];
        }
        rs0 += __shfl_xor_sync(0xffffffffu, rs0, 1);
        rs0 += __shfl_xor_sync(0xffffffffu, rs0, 2);
        rs1 += __shfl_xor_sync(0xffffffffu, rs1, 1);
        rs1 += __shfl_xor_sync(0xffffffffu, rs1, 2);

        l0 = l0 * corr0 + rs0;  m0 = nm0;
        l1 = l1 * corr1 + rs1;  m1 = nm1;

#pragma unroll
        for (int nt = 0; nt < 8; nt++) {
            oacc[nt][0] *= corr0; oacc[nt][1] *= corr0;
            oacc[nt][2] *= corr1; oacc[nt][3] *= corr1;
        }

        // ---- P fragments in registers (FA-2 layout identity) ----
        // A-operand for k-chunk ks: rows g/g+8, keys ks*16 + {2t,2t+1} and +8.
        // Accumulator sacc[nt] holds keys nt*8 + {2t,2t+1} -> nt = 2ks, 2ks+1.
        uint32_t pf[4][4];
#pragma unroll
        for (int ks = 0; ks < 4; ks++) {
            pf[ks][0] = pack_h2(sacc[2 * ks][0],     sacc[2 * ks][1]);
            pf[ks][1] = pack_h2(sacc[2 * ks][2],     sacc[2 * ks][3]);
            pf[ks][2] = pack_h2(sacc[2 * ks + 1][0], sacc[2 * ks + 1][1]);
            pf[ks][3] = pack_h2(sacc[2 * ks + 1][2], sacc[2 * ks + 1][3]);
        }

        // ---- O += P @ V  (fp32 accumulators) ----
        const uint32_t vbase = smem_u32(Vb) + vlane_off * 2;
#pragma unroll
        for (int ks = 0; ks < 4; ks++) {
            const uint32_t vrow = vbase + (uint32_t)(ks * 16 * HPAD * 2);
#pragma unroll
            for (int n16 = 0; n16 < 4; n16++) {
                uint32_t r0, r1, r2, r3;
                ldmatrix_x4_trans(r0, r1, r2, r3, vrow + (uint32_t)(n16 * 32));
                mma_f16(oacc[n16 * 2][0], oacc[n16 * 2][1], oacc[n16 * 2][2], oacc[n16 * 2][3],
                        pf[ks][0], pf[ks][1], pf[ks][2], pf[ks][3], r0, r1);
                mma_f16(oacc[n16 * 2 + 1][0], oacc[n16 * 2 + 1][1],
                        oacc[n16 * 2 + 1][2], oacc[n16 * 2 + 1][3],
                        pf[ks][0], pf[ks][1], pf[ks][2], pf[ks][3], r2, r3);
            }
        }
        __syncthreads();
    }

    const float inv0 = 1.0f / l0;
    const float inv1 = 1.0f / l1;
    const int r0 = q0 + moff + g;
    const int r1 = r0 + 8;
#pragma unroll
    for (int nt = 0; nt < 8; nt++) {
        const int col = nt * 8 + 2 * t;
        *(__half2*)&Og[baso + (size_t)r0 * HID + col] =
            __floats2half2_rn(oacc[nt][0] * inv0, oacc[nt][1] * inv0);
        *(__half2*)&Og[baso + (size_t)r1 * HID + col] =
            __floats2half2_rn(oacc[nt][2] * inv1, oacc[nt][3] * inv1);
    }
}

// ---------------------------------------------------------------------------
// Residual add + LayerNorm.  X fp32, Y fp16.  Optionally emits a half copy.
// ---------------------------------------------------------------------------
template<int HALF_OUT>
__global__ void __launch_bounds__(256) add_ln_kernel(
    const float* __restrict__ X, const __half* __restrict__ Y,
    const float* __restrict__ g, const float* __restrict__ be,
    float* __restrict__ out, __half* __restrict__ outh)
{
    const int row = blockIdx.x;
    const int tid = threadIdx.x;
    const size_t base = (size_t)row * HID;

    float v[4];
    float s = 0.0f, s2 = 0.0f;
#pragma unroll
    for (int k = 0; k < 4; k++) {
        int c = tid + k * 256;
        float tt = X[base + c] + __half2float(Y[base + c]);
        v[k] = tt;
        s += tt;
        s2 += tt * tt;
    }
#pragma unroll
    for (int off = 16; off > 0; off >>= 1) {
        s  += __shfl_xor_sync(0xffffffffu, s,  off);
        s2 += __shfl_xor_sync(0xffffffffu, s2, off);
    }
    __shared__ float red[16];
    const int warp = tid >> 5, lane = tid & 31;
    if (lane == 0) { red[warp] = s; red[warp + 8] = s2; }
    __syncthreads();
    if (tid < 32) {
        float a = (lane < 8) ? red[lane]     : 0.0f;
        float c2 = (lane < 8) ? red[lane + 8] : 0.0f;
#pragma unroll
        for (int off = 4; off > 0; off >>= 1) {
            a  += __shfl_xor_sync(0xffffffffu, a,  off);
            c2 += __shfl_xor_sync(0xffffffffu, c2, off);
        }
        if (lane == 0) { red[0] = a; red[1] = c2; }
    }
    __syncthreads();
    const float mu  = red[0] * (1.0f / HID);
    const float var = red[1] * (1.0f / HID) - mu * mu;
    const float inv = rsqrtf(var + 1e-5f);
#pragma unroll
    for (int k = 0; k < 4; k++) {
        int c = tid + k * 256;
        float r = (v[k] - mu) * inv * g[c] + be[c];
        out[base + c] = r;
        if (HALF_OUT) outh[base + c] = __float2half_rn(r);
    }
}

// ---------------------------------------------------------------------------
// kernel_launch
// ---------------------------------------------------------------------------
extern "C" void kernel_launch(void* const* d_in, const int* in_sizes, int n_in,
                              void* d_out, int out_size)
{
    const float* x  = (const float*)d_in[0];
    const float* Wq = (const float*)d_in[1];
    const float* bq = (const float*)d_in[2];
    const float* Wk = (const float*)d_in[3];
    const float* bk = (const float*)d_in[4];
    const float* Wv = (const float*)d_in[5];
    const float* bv = (const float*)d_in[6];
    const float* Wo = (const float*)d_in[7];
    const float* bo = (const float*)d_in[8];
    const float* W1 = (const float*)d_in[9];
    const float* b1 = (const float*)d_in[10];
    const float* W2 = (const float*)d_in[11];
    const float* b2 = (const float*)d_in[12];
    const float* g1 = (const float*)d_in[13];
    const float* be1= (const float*)d_in[14];
    const float* g2 = (const float*)d_in[15];
    const float* be2= (const float*)d_in[16];
    float* out = (float*)d_out;

    __half *xh, *qkvh, *ctxh, *aoh, *x1h, *hh, *ffh;
    float *x1, *bqkv;
    __half *wqkvt, *wot, *w1t, *w2t;
    cudaGetSymbolAddress((void**)&xh,    g_xh);
    cudaGetSymbolAddress((void**)&qkvh,  g_qkvh);
    cudaGetSymbolAddress((void**)&ctxh,  g_ctxh);
    cudaGetSymbolAddress((void**)&aoh,   g_aoh);
    cudaGetSymbolAddress((void**)&x1,    g_x1);
    cudaGetSymbolAddress((void**)&x1h,   g_x1h);
    cudaGetSymbolAddress((void**)&hh,    g_hh);
    cudaGetSymbolAddress((void**)&ffh,   g_ffh);
    cudaGetSymbolAddress((void**)&wqkvt, g_wqkvt);
    cudaGetSymbolAddress((void**)&wot,   g_wot);
    cudaGetSymbolAddress((void**)&w1t,   g_w1t);
    cudaGetSymbolAddress((void**)&w2t,   g_w2t);
    cudaGetSymbolAddress((void**)&bqkv,  g_bqkv);

    cudaFuncSetAttribute(attn_mma_h_kernel,
                         cudaFuncAttributeMaxDynamicSharedMemorySize, ATT_SMEM);
    cudaFuncSetAttribute(mma_gemm_h<1>,
                         cudaFuncAttributeMaxDynamicSharedMemorySize, GEMM_SMEM);
    cudaFuncSetAttribute(mma_gemm_h<2>,
                         cudaFuncAttributeMaxDynamicSharedMemorySize, GEMM_SMEM);
    cudaFuncSetAttribute(mma_gemm_h<3>,
                         cudaFuncAttributeMaxDynamicSharedMemorySize, GEMM_SMEM);

    const dim3 blk256(256);

    // fork: side stream for Wo/W1/W2 prep (overlaps QKV GEMM + attention)
    cudaStream_t s1;
    cudaEvent_t evFork, evJoin;
    cudaStreamCreateWithFlags(&s1, cudaStreamNonBlocking);
    cudaEventCreateWithFlags(&evFork, cudaEventDisableTiming);
    cudaEventCreateWithFlags(&evJoin, cudaEventDisableTiming);

    cudaEventRecord(evFork, 0);
    cudaStreamWaitEvent(s1, evFork, 0);
    prep_b_kernel<<<9216, blk256, 0, s1>>>(Wo, W1, W2);
    cudaEventRecord(evJoin, s1);

    // main stream: QKV path
    prep_a_kernel<<<7180, blk256>>>(Wq, Wk, Wv, x, bq, bk, bv);

    // fused QKV GEMM (Q columns pre-scaled by 0.125)
    mma_gemm_h<3><<<dim3(NQKV / BN, MTOT / BM), blk256, GEMM_SMEM>>>(
        xh, wqkvt, bqkv, qkvh, MTOT, NQKV, HID);

    // attention
    attn_mma_h_kernel<<<dim3(SEQ / BQ, NHEAD, BATCH), blk256, ATT_SMEM>>>(qkvh, ctxh);

    // join: Wo/W1/W2 weights must be ready from here on
    cudaStreamWaitEvent(0, evJoin, 0);

    const dim3 gProj(HID / BN, MTOT / BM);   // (8, 64)
    const dim3 gFF1 (DFF / BN, MTOT / BM);   // (32, 64)

    // output projection (half out) + residual/LN1 (fp32 + half copies)
    mma_gemm_h<1><<<gProj, blk256, GEMM_SMEM>>>(ctxh, wot, bo, aoh, MTOT, HID, HID);
    add_ln_kernel<1><<<MTOT, blk256>>>(x, aoh, g1, be1, x1, x1h);

    // FFN
    mma_gemm_h<2><<<gFF1, blk256, GEMM_SMEM>>>(x1h, w1t, b1, hh, MTOT, DFF, HID);
    mma_gemm_h<1><<<gProj, blk256, GEMM_SMEM>>>(hh, w2t, b2, ffh, MTOT, HID, DFF);

    // residual/LN2 -> output
    add_ln_kernel<0><<<MTOT, blk256>>>(x1, ffh, g2, be2, out, nullptr);
}